// round 9
// baseline (speedup 1.0000x reference)
#include <cuda_runtime.h>
#include <math.h>

#define B 2
#define H 8
#define BH 16
#define S 4096
#define D 64
#define EPS 1e-12f
#define NCHUNK 64
#define CHUNK (S / NCHUNK)      // 64 key rows per accum block
#define NPART NCHUNK            // one M-partial per accum block
#define NQ 32
#define QROWS (S / NQ)          // 128 query rows per output block

typedef unsigned long long u64;
union F2 { u64 u; float2 f; };

// Scratch (no cudaMalloc allowed) -------------------------------------------
// M partials in "d-paired" layout: u64 index u = d2*64 + e holds
// (M[2*d2][e], M[2*d2+1][e]).
__device__ ulonglong2 g_Mpart[BH][NPART][D * D / 4];
__device__ float4     g_Kpart[BH][NCHUNK][D / 4];
__device__ float4     g_Vpart[BH][NCHUNK][D / 4];
__device__ float      g_cntpart[BH][NCHUNK];

__device__ float  g_Mfin[BH][D][D];       // unpaired [d][e]
__device__ float4 g_Ksf[BH][D / 4];
__device__ float4 g_Vsf[BH][D / 4];
__device__ float  g_cntf[BH];

// ---------------------------------------------------------------------------
__device__ __forceinline__ u64 ffma2(u64 a, u64 b, u64 c) {
    u64 d;
    asm("fma.rn.f32x2 %0, %1, %2, %3;" : "=l"(d) : "l"(a), "l"(b), "l"(c));
    return d;
}
__device__ __forceinline__ u64 splat2(float s) {
    u64 d;
    asm("mov.b64 %0, {%1, %1};" : "=l"(d) : "r"(__float_as_uint(s)));
    return d;
}
__device__ __forceinline__ float dot4(float4 a, float4 b) {
    return a.x * b.x + a.y * b.y + a.z * b.z + a.w * b.w;
}
#define ADD4(a, v) { a.x += (v).x; a.y += (v).y; a.z += (v).z; a.w += (v).w; }

// ===========================================================================
// Kernel 1: per-(bh,chunk) partial of M = sum khat v^T, plus Ks, Vs, cnt.
// grid (BH, NCHUNK) = 1024 blocks, 128 threads, 32KB smem -> 7 blocks/SM,
// single wave.  Phase A stages 64 rows (no inner barriers); Phase B is a
// 64-step GEMM, thread (td8, te) owns 8d x 4e, FFMA2-paired along d,
// with manual next-step prefetch.
// ===========================================================================
__global__ __launch_bounds__(128, 7) void accum_kernel(
    const float* __restrict__ Kt, const float* __restrict__ Vt,
    const int* __restrict__ mask)
{
    extern __shared__ float smem[];
    float* sk = smem;                 // [64][64]  16KB
    float* sv = smem + CHUNK * D;     // [64][64]  16KB
    __shared__ float scred[8];

    const int bh   = blockIdx.x;
    const int ck   = blockIdx.y;
    const int b    = bh / H;
    const int tid  = threadIdx.x;
    const int slot = tid >> 4;        // row-within-pass 0..7
    const int hl   = tid & 15;        // float4 quarter of the row

    const float4* Kbh = (const float4*)(Kt + (size_t)bh * S * D);
    const float4* Vbh = (const float4*)(Vt + (size_t)bh * S * D);
    const int*    mb  = mask + (size_t)b * S;
    const int     row0 = ck * CHUNK;

    // ---- Phase A: stage 64 rows, no barriers ------------------------------
    float4 ksum = make_float4(0.f, 0.f, 0.f, 0.f);
    float4 vsum = make_float4(0.f, 0.f, 0.f, 0.f);
    float  cacc = 0.f;

    #pragma unroll
    for (int p = 0; p < CHUNK / 8; p++) {
        const int r   = p * 8 + slot;
        const int row = row0 + r;
        float4 k4 = Kbh[row * 16 + hl];
        float4 v4 = Vbh[row * 16 + hl];
        float  ss = dot4(k4, k4);
        #pragma unroll
        for (int o = 1; o < 16; o <<= 1) ss += __shfl_xor_sync(0xffffffffu, ss, o);
        const float m  = (float)mb[row];
        const float sc = m / fmaxf(sqrtf(ss), EPS);
        float4 kh = make_float4(k4.x * sc, k4.y * sc, k4.z * sc, k4.w * sc);
        float4 vm = make_float4(v4.x * m, v4.y * m, v4.z * m, v4.w * m);
        *(float4*)&sk[r * 64 + 4 * hl] = kh;
        *(float4*)&sv[r * 64 + 4 * hl] = vm;
        ADD4(ksum, kh);
        ADD4(vsum, vm);
        if (hl == 0) cacc += m;
    }
    __syncthreads();

    // ---- Phase B: 64-step rank-1 accumulation, 8d x 4e per thread ---------
    const int td8 = tid >> 4;         // d-group (8 d), 0..7
    const int te  = tid & 15;         // e-group (4 e), 0..15

    const ulonglong2* K2 = (const ulonglong2*)sk;   // row = 16 ul2
    const float4*     V4 = (const float4*)sv;       // row = 16 float4

    u64 acc[4][4];                    // [d-pair][e]
    #pragma unroll
    for (int i = 0; i < 4; i++)
        #pragma unroll
        for (int j = 0; j < 4; j++) acc[i][j] = 0ull;

    ulonglong2 kpa = K2[2 * td8];
    ulonglong2 kpb = K2[2 * td8 + 1];
    float4     vec = V4[te];

    #pragma unroll 4
    for (int k = 0; k < CHUNK; k++) {
        const ulonglong2 ca = kpa, cb = kpb;
        const float4     cv = vec;
        const int kn = (k + 1 < CHUNK) ? k + 1 : k;
        kpa = K2[kn * 16 + 2 * td8];
        kpb = K2[kn * 16 + 2 * td8 + 1];
        vec = V4[kn * 16 + te];

        const u64 s0 = splat2(cv.x), s1 = splat2(cv.y);
        const u64 s2 = splat2(cv.z), s3 = splat2(cv.w);
        acc[0][0] = ffma2(ca.x, s0, acc[0][0]);
        acc[0][1] = ffma2(ca.x, s1, acc[0][1]);
        acc[0][2] = ffma2(ca.x, s2, acc[0][2]);
        acc[0][3] = ffma2(ca.x, s3, acc[0][3]);
        acc[1][0] = ffma2(ca.y, s0, acc[1][0]);
        acc[1][1] = ffma2(ca.y, s1, acc[1][1]);
        acc[1][2] = ffma2(ca.y, s2, acc[1][2]);
        acc[1][3] = ffma2(ca.y, s3, acc[1][3]);
        acc[2][0] = ffma2(cb.x, s0, acc[2][0]);
        acc[2][1] = ffma2(cb.x, s1, acc[2][1]);
        acc[2][2] = ffma2(cb.x, s2, acc[2][2]);
        acc[2][3] = ffma2(cb.x, s3, acc[2][3]);
        acc[3][0] = ffma2(cb.y, s0, acc[3][0]);
        acc[3][1] = ffma2(cb.y, s1, acc[3][1]);
        acc[3][2] = ffma2(cb.y, s2, acc[3][2]);
        acc[3][3] = ffma2(cb.y, s3, acc[3][3]);
    }

    // ---- flush M partial (paired layout: u64 u = d2*64+e) -----------------
    {
        ulonglong2* Mout = g_Mpart[bh][ck];
        #pragma unroll
        for (int i = 0; i < 4; i++) {
            const int d2 = 4 * td8 + i;           // covers d = 8td8+2i, +2i+1
            const int p0 = d2 * 32 + 2 * te;      // ulonglong2 index
            Mout[p0]     = make_ulonglong2(acc[i][0], acc[i][1]);
            Mout[p0 + 1] = make_ulonglong2(acc[i][2], acc[i][3]);
        }
    }

    // ---- reduce Ks/Vs/cnt through smem (reuse staging space) --------------
    __syncthreads();
    ((float4*)sk)[tid] = ksum;
    ((float4*)sv)[tid] = vsum;
    if (hl == 0) scred[slot] = cacc;
    __syncthreads();
    if (tid < 16) {
        float4 s = make_float4(0.f, 0.f, 0.f, 0.f);
        #pragma unroll
        for (int sl = 0; sl < 8; sl++) { float4 p = ((float4*)sk)[sl * 16 + tid]; ADD4(s, p); }
        g_Kpart[bh][ck][tid] = s;
    } else if (tid < 32) {
        float4 s = make_float4(0.f, 0.f, 0.f, 0.f);
        #pragma unroll
        for (int sl = 0; sl < 8; sl++) { float4 p = ((float4*)sv)[sl * 16 + tid - 16]; ADD4(s, p); }
        g_Vpart[bh][ck][tid - 16] = s;
    } else if (tid == 32) {
        float c = 0.f;
        #pragma unroll
        for (int i = 0; i < 8; i++) c += scred[i];
        g_cntpart[bh][ck] = c;
    }
}

// ===========================================================================
// Kernel 2: reduce partials; un-pair M into g_Mfin[d][e].
// grid (BH, 4), block 256 (each partial = 1024 float4s).
// ===========================================================================
__global__ __launch_bounds__(256) void reduce_kernel()
{
    const int bh  = blockIdx.x;
    const int yb  = blockIdx.y;
    const int tid = threadIdx.x;
    const int j   = yb * 256 + tid;   // float4 index 0..1023 within a partial

    float4 a = make_float4(0.f, 0.f, 0.f, 0.f);
    #pragma unroll 16
    for (int c = 0; c < NPART; c++) {
        float4 p = ((const float4*)g_Mpart[bh][c])[j];
        ADD4(a, p);
    }
    // float4 j = u64s {2j, 2j+1}: u0 = 2j -> d2 = u0>>6, e0 = u0&63 (even)
    const int u0 = 2 * j;
    const int d2 = u0 >> 6;           // 0..31
    const int e0 = u0 & 63;           // even, 0..62
    g_Mfin[bh][2 * d2][e0]         = a.x;
    g_Mfin[bh][2 * d2 + 1][e0]     = a.y;
    g_Mfin[bh][2 * d2][e0 + 1]     = a.z;
    g_Mfin[bh][2 * d2 + 1][e0 + 1] = a.w;

    if (yb == 0) {
        if (tid < 16) {
            float4 s = make_float4(0.f, 0.f, 0.f, 0.f);
            #pragma unroll
            for (int c = 0; c < NCHUNK; c++) { float4 p = g_Kpart[bh][c][tid]; ADD4(s, p); }
            g_Ksf[bh][tid] = s;
        } else if (tid < 32) {
            float4 s = make_float4(0.f, 0.f, 0.f, 0.f);
            #pragma unroll
            for (int c = 0; c < NCHUNK; c++) { float4 p = g_Vpart[bh][c][tid - 16]; ADD4(s, p); }
            g_Vsf[bh][tid - 16] = s;
        } else if (tid == 32) {
            float c0 = 0.f;
            #pragma unroll
            for (int c = 0; c < NCHUNK; c++) c0 += g_cntpart[bh][c];
            g_cntf[bh] = c0;
        }
    }
}

// ===========================================================================
// Kernel 3: out[q,e] = (qhat . M[:,e] + Vs[e]) / (qhat . Ks + cnt)
// grid (BH, NQ), block 256.  2 passes x 64 rows; thread owns 4x4 output tile
// (round-4 proven version).
// ===========================================================================
#define QT_STRIDE 68   // multiple of 4 (16B-aligned LDS.128), breaks bank repeats

__global__ __launch_bounds__(256) void output_kernel(
    const float* __restrict__ Qt, float* __restrict__ out)
{
    const int bh  = blockIdx.x;
    const int qb  = blockIdx.y;
    const int tid = threadIdx.x;

    __shared__ float sM[D][D];                // 16KB  [d][e]
    __shared__ float sqT[D][QT_STRIDE];       // 17KB  [d][row]
    __shared__ float sKs[D];
    __shared__ float sVs[D];
    __shared__ float sden[64];
    __shared__ float scnt;

    // ---- preamble: final M / Ks / Vs / cnt --------------------------------
    {
        float4* sM4 = (float4*)sM;
        const float4* Mf = (const float4*)g_Mfin[bh];
        #pragma unroll
        for (int t = 0; t < 4; t++) sM4[tid + 256 * t] = Mf[tid + 256 * t];
        if (tid < 16)       ((float4*)sKs)[tid]      = g_Ksf[bh][tid];
        else if (tid < 32)  ((float4*)sVs)[tid - 16] = g_Vsf[bh][tid - 16];
        else if (tid == 32) scnt = g_cntf[bh];
    }
    __syncthreads();

    const float4* Qbh = (const float4*)(Qt + (size_t)bh * S * D);
    float*        Obh = out + (size_t)bh * S * D;

    const int srow = tid >> 2;        // staging: row 0..63
    const int part = tid & 3;         // staging: quarter of the row
    const int tc   = tid & 15;        // mainloop: col group (4 e)
    const int tr   = tid >> 4;        // mainloop: row group (4 rows)
    const float cnt = scnt;
    const float4 vs = ((float4*)sVs)[tc];

    for (int p = 0; p < 2; p++) {
        const int rowbase = qb * QROWS + p * 64;

        // ---- stage 64 rows: normalize, transpose, denominator -------------
        {
            const int row = rowbase + srow;
            float4 qv[4];
            float ss = 0.f, dk = 0.f;
            #pragma unroll
            for (int t = 0; t < 4; t++) {
                float4 qq = Qbh[row * 16 + part + 4 * t];
                qv[t] = qq;
                ss += dot4(qq, qq);
                dk += dot4(qq, ((float4*)sKs)[part + 4 * t]);
            }
            ss += __shfl_xor_sync(0xffffffffu, ss, 1);
            ss += __shfl_xor_sync(0xffffffffu, ss, 2);
            dk += __shfl_xor_sync(0xffffffffu, dk, 1);
            dk += __shfl_xor_sync(0xffffffffu, dk, 2);
            const float sc = 1.f / fmaxf(sqrtf(ss), EPS);
            #pragma unroll
            for (int t = 0; t < 4; t++) {
                const int d0 = 4 * (part + 4 * t);
                sqT[d0 + 0][srow] = qv[t].x * sc;
                sqT[d0 + 1][srow] = qv[t].y * sc;
                sqT[d0 + 2][srow] = qv[t].z * sc;
                sqT[d0 + 3][srow] = qv[t].w * sc;
            }
            if (part == 0) sden[srow] = dk * sc + cnt;
        }
        __syncthreads();

        // ---- 4x4 register-tiled GEMM: Out = qhat^T-chunk x M --------------
        u64 accA[4], accB[4];
        #pragma unroll
        for (int r = 0; r < 4; r++) { accA[r] = 0ull; accB[r] = 0ull; }

        #pragma unroll 16
        for (int k = 0; k < D; k++) {
            const float4     qv = *(const float4*)&sqT[k][4 * tr];   // broadcast
            const ulonglong2 mm = *(const ulonglong2*)&sM[k][4 * tc];
            const u64 s0 = splat2(qv.x), s1 = splat2(qv.y);
            const u64 s2 = splat2(qv.z), s3 = splat2(qv.w);
            accA[0] = ffma2(s0, mm.x, accA[0]); accB[0] = ffma2(s0, mm.y, accB[0]);
            accA[1] = ffma2(s1, mm.x, accA[1]); accB[1] = ffma2(s1, mm.y, accB[1]);
            accA[2] = ffma2(s2, mm.x, accA[2]); accB[2] = ffma2(s2, mm.y, accB[2]);
            accA[3] = ffma2(s3, mm.x, accA[3]); accB[3] = ffma2(s3, mm.y, accB[3]);
        }

        // ---- epilogue ------------------------------------------------------
        #pragma unroll
        for (int r = 0; r < 4; r++) {
            const int row = rowbase + 4 * tr + r;
            const float inv = 1.f / sden[4 * tr + r];
            F2 a, bb; a.u = accA[r]; bb.u = accB[r];
            float4 o = make_float4((a.f.x + vs.x) * inv, (a.f.y + vs.y) * inv,
                                   (bb.f.x + vs.z) * inv, (bb.f.y + vs.w) * inv);
            *(float4*)&Obh[row * 64 + 4 * tc] = o;
        }
        __syncthreads();
    }
}

// ===========================================================================
extern "C" void kernel_launch(void* const* d_in, const int* in_sizes, int n_in,
                              void* d_out, int out_size)
{
    const float* q    = (const float*)d_in[0];
    const float* k    = (const float*)d_in[1];
    const float* v    = (const float*)d_in[2];
    const int*   mask = (const int*)d_in[3];
    float* out = (float*)d_out;

    const int accum_smem = 2 * CHUNK * D * sizeof(float);   // 32KB
    cudaFuncSetAttribute(accum_kernel,
                         cudaFuncAttributeMaxDynamicSharedMemorySize, accum_smem);

    accum_kernel<<<dim3(BH, NCHUNK), 128, accum_smem>>>(k, v, mask);
    reduce_kernel<<<dim3(BH, 4), 256>>>();
    output_kernel<<<dim3(BH, NQ), 256>>>(q, out);
}

// round 11
// speedup vs baseline: 1.2574x; 1.2574x over previous
#include <cuda_runtime.h>
#include <math.h>

#define B 2
#define H 8
#define BH 16
#define S 4096
#define D 64
#define EPS 1e-12f
#define NCHUNK 32
#define CHUNK (S / NCHUNK)      // 128 key rows per accum block
#define TILE 16
#define NTILE (CHUNK / TILE)    // 8 tiles
#define NPART NCHUNK            // one M-partial per accum block
#define NQ 32
#define QROWS (S / NQ)          // 128 query rows per output block

typedef unsigned long long u64;
union F2 { u64 u; float2 f; };

// Scratch (no cudaMalloc allowed) -------------------------------------------
// M partials in "d-paired" layout: u64 index u = d2*64 + e holds
// (M[2*d2][e], M[2*d2+1][e]).
__device__ ulonglong2 g_Mpart[BH][NPART][D * D / 4];
__device__ float4     g_Kpart[BH][NPART][D / 4];
__device__ float4     g_Vpart[BH][NPART][D / 4];
__device__ float      g_cntpart[BH][NPART];

__device__ float  g_Mfin[BH][D][D];       // unpaired [d][e]
__device__ float4 g_Ksf[BH][D / 4];
__device__ float4 g_Vsf[BH][D / 4];
__device__ float  g_cntf[BH];

// ---------------------------------------------------------------------------
__device__ __forceinline__ u64 ffma2(u64 a, u64 b, u64 c) {
    u64 d;
    asm("fma.rn.f32x2 %0, %1, %2, %3;" : "=l"(d) : "l"(a), "l"(b), "l"(c));
    return d;
}
__device__ __forceinline__ u64 splat2(float s) {
    u64 d;
    asm("mov.b64 %0, {%1, %1};" : "=l"(d) : "r"(__float_as_uint(s)));
    return d;
}
__device__ __forceinline__ float dot4(float4 a, float4 b) {
    return a.x * b.x + a.y * b.y + a.z * b.z + a.w * b.w;
}
#define ADD4(a, v) { a.x += (v).x; a.y += (v).y; a.z += (v).z; a.w += (v).w; }

// ===========================================================================
// Kernel 1: per-(bh,chunk) partial of M = sum khat v^T, plus Ks, Vs, cnt.
// grid (BH, 32) = 512 blocks, 128 threads, static smem ~16.5KB.
// Software-pipelined: while GEMM consumes tile t from smem, tile t+1's
// LDG.128s are in flight into registers; normalize+store after the GEMM.
// GEMM thread (td8, te) owns 8d x 4e, FFMA2-paired along d.
// ===========================================================================
__global__ __launch_bounds__(128) void accum_kernel(
    const float* __restrict__ Kt, const float* __restrict__ Vt,
    const int* __restrict__ mask)
{
    __shared__ float bufK[2][TILE][64];   // 8KB
    __shared__ float bufV[2][TILE][64];   // 8KB
    __shared__ float scred[16];

    const int bh  = blockIdx.x;
    const int ck  = blockIdx.y;
    const int b   = bh / H;
    const int tid = threadIdx.x;
    const int r8  = tid >> 3;        // staging row in tile, 0..15
    const int q8  = tid & 7;         // eighth of the row
    const int td8 = tid >> 4;        // d-group (8 d), 0..7
    const int te  = tid & 15;        // e-group (4 e), 0..15

    const float4* Kbh = (const float4*)(Kt + (size_t)bh * S * D);
    const float4* Vbh = (const float4*)(Vt + (size_t)bh * S * D);
    const int*    mb  = mask + (size_t)b * S;
    const int     row0 = ck * CHUNK;

    float4 ksA = make_float4(0.f,0.f,0.f,0.f), ksB = ksA;
    float4 vsA = ksA, vsB = ksA;
    float  cacc = 0.f;

    float* curK = &bufK[0][0][0];
    float* curV = &bufV[0][0][0];
    float* nxtK = &bufK[1][0][0];
    float* nxtV = &bufV[1][0][0];

    u64 acc[4][4];
    #pragma unroll
    for (int i = 0; i < 4; i++)
        #pragma unroll
        for (int j = 0; j < 4; j++) acc[i][j] = 0ull;

    float4 k0, k1, v0, v1;

    // ---- prologue: load + normalize + store tile 0 ------------------------
    {
        const int row = row0 + r8;
        const float4* kp = &Kbh[row * 16 + 2 * q8];
        const float4* vp = &Vbh[row * 16 + 2 * q8];
        k0 = kp[0]; k1 = kp[1];
        v0 = vp[0]; v1 = vp[1];
        float ss = dot4(k0, k0) + dot4(k1, k1);
        ss += __shfl_xor_sync(0xffffffffu, ss, 1);
        ss += __shfl_xor_sync(0xffffffffu, ss, 2);
        ss += __shfl_xor_sync(0xffffffffu, ss, 4);
        const float m  = (float)mb[row];
        const float sc = m / fmaxf(sqrtf(ss), EPS);
        float4 kh0 = make_float4(k0.x*sc, k0.y*sc, k0.z*sc, k0.w*sc);
        float4 kh1 = make_float4(k1.x*sc, k1.y*sc, k1.z*sc, k1.w*sc);
        float4 vm0 = make_float4(v0.x*m, v0.y*m, v0.z*m, v0.w*m);
        float4 vm1 = make_float4(v1.x*m, v1.y*m, v1.z*m, v1.w*m);
        *(float4*)&curK[r8 * 64 + 8 * q8]     = kh0;
        *(float4*)&curK[r8 * 64 + 8 * q8 + 4] = kh1;
        *(float4*)&curV[r8 * 64 + 8 * q8]     = vm0;
        *(float4*)&curV[r8 * 64 + 8 * q8 + 4] = vm1;
        ADD4(ksA, kh0); ADD4(ksB, kh1);
        ADD4(vsA, vm0); ADD4(vsB, vm1);
        if (q8 == 0) cacc += m;
    }
    __syncthreads();

    // ---- pipelined mainloop ------------------------------------------------
    const int kOff = 8 * td8;         // float offset of this thread's K pair
    const int vOff = 4 * te;          // float offset of this thread's V quad

    for (int t = 0; t < NTILE; t++) {
        // issue next tile's loads (results consumed after the GEMM)
        if (t + 1 < NTILE) {
            const int row = row0 + (t + 1) * TILE + r8;
            const float4* kp = &Kbh[row * 16 + 2 * q8];
            const float4* vp = &Vbh[row * 16 + 2 * q8];
            k0 = kp[0]; k1 = kp[1];
            v0 = vp[0]; v1 = vp[1];
        }

        // GEMM: 16 rank-1 steps from current buffer (immediate LDS offsets)
        const float* cK = curK + kOff;
        const float* cV = curV + vOff;
        #pragma unroll
        for (int k = 0; k < TILE; k++) {
            const ulonglong2 ka = *(const ulonglong2*)(cK + k * 64);
            const ulonglong2 kb = *(const ulonglong2*)(cK + k * 64 + 4);
            const float4     ve = *(const float4*)(cV + k * 64);
            const u64 s0 = splat2(ve.x), s1 = splat2(ve.y);
            const u64 s2 = splat2(ve.z), s3 = splat2(ve.w);
            acc[0][0] = ffma2(ka.x, s0, acc[0][0]);
            acc[0][1] = ffma2(ka.x, s1, acc[0][1]);
            acc[0][2] = ffma2(ka.x, s2, acc[0][2]);
            acc[0][3] = ffma2(ka.x, s3, acc[0][3]);
            acc[1][0] = ffma2(ka.y, s0, acc[1][0]);
            acc[1][1] = ffma2(ka.y, s1, acc[1][1]);
            acc[1][2] = ffma2(ka.y, s2, acc[1][2]);
            acc[1][3] = ffma2(ka.y, s3, acc[1][3]);
            acc[2][0] = ffma2(kb.x, s0, acc[2][0]);
            acc[2][1] = ffma2(kb.x, s1, acc[2][1]);
            acc[2][2] = ffma2(kb.x, s2, acc[2][2]);
            acc[2][3] = ffma2(kb.x, s3, acc[2][3]);
            acc[3][0] = ffma2(kb.y, s0, acc[3][0]);
            acc[3][1] = ffma2(kb.y, s1, acc[3][1]);
            acc[3][2] = ffma2(kb.y, s2, acc[3][2]);
            acc[3][3] = ffma2(kb.y, s3, acc[3][3]);
        }

        // normalize + store next tile (LDG latency now amortized)
        if (t + 1 < NTILE) {
            const int row = row0 + (t + 1) * TILE + r8;
            float ss = dot4(k0, k0) + dot4(k1, k1);
            ss += __shfl_xor_sync(0xffffffffu, ss, 1);
            ss += __shfl_xor_sync(0xffffffffu, ss, 2);
            ss += __shfl_xor_sync(0xffffffffu, ss, 4);
            const float m  = (float)mb[row];
            const float sc = m / fmaxf(sqrtf(ss), EPS);
            float4 kh0 = make_float4(k0.x*sc, k0.y*sc, k0.z*sc, k0.w*sc);
            float4 kh1 = make_float4(k1.x*sc, k1.y*sc, k1.z*sc, k1.w*sc);
            float4 vm0 = make_float4(v0.x*m, v0.y*m, v0.z*m, v0.w*m);
            float4 vm1 = make_float4(v1.x*m, v1.y*m, v1.z*m, v1.w*m);
            *(float4*)&nxtK[r8 * 64 + 8 * q8]     = kh0;
            *(float4*)&nxtK[r8 * 64 + 8 * q8 + 4] = kh1;
            *(float4*)&nxtV[r8 * 64 + 8 * q8]     = vm0;
            *(float4*)&nxtV[r8 * 64 + 8 * q8 + 4] = vm1;
            ADD4(ksA, kh0); ADD4(ksB, kh1);
            ADD4(vsA, vm0); ADD4(vsB, vm1);
            if (q8 == 0) cacc += m;
        }
        // swap buffers
        float* tK = curK; curK = nxtK; nxtK = tK;
        float* tV = curV; curV = nxtV; nxtV = tV;
        __syncthreads();
    }

    // ---- flush M partial (paired layout: u64 u = d2*64+e) -----------------
    {
        ulonglong2* Mout = g_Mpart[bh][ck];
        #pragma unroll
        for (int i = 0; i < 4; i++) {
            const int d2 = 4 * td8 + i;           // covers d = 8td8+2i, +2i+1
            const int p0 = d2 * 32 + 2 * te;      // ulonglong2 index
            Mout[p0]     = make_ulonglong2(acc[i][0], acc[i][1]);
            Mout[p0 + 1] = make_ulonglong2(acc[i][2], acc[i][3]);
        }
    }

    // ---- reduce Ks/Vs/cnt through smem (reuse buffers) --------------------
    __syncthreads();
    float4* redK = (float4*)bufK;     // [128][2] float4
    float4* redV = (float4*)bufV;
    redK[2 * tid]     = ksA;
    redK[2 * tid + 1] = ksB;
    redV[2 * tid]     = vsA;
    redV[2 * tid + 1] = vsB;
    if (q8 == 0) scred[r8] = cacc;
    __syncthreads();
    if (tid < 16) {
        // f4 index f = tid: contributors are threads row*8 + (f>>1), slot f&1
        float4 s = make_float4(0.f, 0.f, 0.f, 0.f);
        #pragma unroll
        for (int row = 0; row < 16; row++) {
            float4 p = redK[2 * (row * 8 + (tid >> 1)) + (tid & 1)];
            ADD4(s, p);
        }
        g_Kpart[bh][ck][tid] = s;
    } else if (tid < 32) {
        const int f = tid - 16;
        float4 s = make_float4(0.f, 0.f, 0.f, 0.f);
        #pragma unroll
        for (int row = 0; row < 16; row++) {
            float4 p = redV[2 * (row * 8 + (f >> 1)) + (f & 1)];
            ADD4(s, p);
        }
        g_Vpart[bh][ck][f] = s;
    } else if (tid == 32) {
        float c = 0.f;
        #pragma unroll
        for (int i = 0; i < 16; i++) c += scred[i];
        g_cntpart[bh][ck] = c;
    }
}

// ===========================================================================
// Kernel 2: reduce partials; un-pair M into g_Mfin[d][e].
// grid (BH, 4), block 256 (each partial = 1024 float4s).
// ===========================================================================
__global__ __launch_bounds__(256) void reduce_kernel()
{
    const int bh  = blockIdx.x;
    const int yb  = blockIdx.y;
    const int tid = threadIdx.x;
    const int j   = yb * 256 + tid;   // float4 index 0..1023 within a partial

    float4 a = make_float4(0.f, 0.f, 0.f, 0.f);
    #pragma unroll 8
    for (int c = 0; c < NPART; c++) {
        float4 p = ((const float4*)g_Mpart[bh][c])[j];
        ADD4(a, p);
    }
    // float4 j = u64s {2j, 2j+1}: u0 = 2j -> d2 = u0>>6, e0 = u0&63 (even)
    const int u0 = 2 * j;
    const int d2 = u0 >> 6;           // 0..31
    const int e0 = u0 & 63;           // even, 0..62
    g_Mfin[bh][2 * d2][e0]         = a.x;
    g_Mfin[bh][2 * d2 + 1][e0]     = a.y;
    g_Mfin[bh][2 * d2][e0 + 1]     = a.z;
    g_Mfin[bh][2 * d2 + 1][e0 + 1] = a.w;

    if (yb == 0) {
        if (tid < 16) {
            float4 s = make_float4(0.f, 0.f, 0.f, 0.f);
            #pragma unroll
            for (int c = 0; c < NPART; c++) { float4 p = g_Kpart[bh][c][tid]; ADD4(s, p); }
            g_Ksf[bh][tid] = s;
        } else if (tid < 32) {
            float4 s = make_float4(0.f, 0.f, 0.f, 0.f);
            #pragma unroll
            for (int c = 0; c < NPART; c++) { float4 p = g_Vpart[bh][c][tid - 16]; ADD4(s, p); }
            g_Vsf[bh][tid - 16] = s;
        } else if (tid == 32) {
            float c0 = 0.f;
            #pragma unroll
            for (int c = 0; c < NPART; c++) c0 += g_cntpart[bh][c];
            g_cntf[bh] = c0;
        }
    }
}

// ===========================================================================
// Kernel 3: out[q,e] = (qhat . M[:,e] + Vs[e]) / (qhat . Ks + cnt)
// grid (BH, NQ), block 256, 128 rows per block in ONE pass.
// GEMM thread owns 8 rows x 4 e, FFMA2-paired along rows (sqT transposed).
// (round-7 proven version)
// ===========================================================================
#define QT_ST 132   // multiple of 4 (16B-aligned LDS.128)

__global__ __launch_bounds__(256) void output_kernel(
    const float* __restrict__ Qt, float* __restrict__ out)
{
    const int bh  = blockIdx.x;
    const int qb  = blockIdx.y;
    const int tid = threadIdx.x;

    __shared__ float sM[D][D];          // 16KB [d][e]
    __shared__ float sqT[D][QT_ST];     // ~34KB [d][row]
    __shared__ float sKs[D];
    __shared__ float sVs[D];
    __shared__ float sden[128];
    __shared__ float scnt;

    // ---- preamble: final M / Ks / Vs / cnt --------------------------------
    {
        float4* sM4 = (float4*)sM;
        const float4* Mf = (const float4*)g_Mfin[bh];
        #pragma unroll
        for (int t = 0; t < 4; t++) sM4[tid + 256 * t] = Mf[tid + 256 * t];
        if (tid < 16)       ((float4*)sKs)[tid]      = g_Ksf[bh][tid];
        else if (tid < 32)  ((float4*)sVs)[tid - 16] = g_Vsf[bh][tid - 16];
        else if (tid == 32) scnt = g_cntf[bh];
    }
    __syncthreads();

    const float4* Qbh = (const float4*)(Qt + (size_t)bh * S * D);
    float*        Obh = out + (size_t)bh * S * D;
    const float   cnt = scnt;
    const int     part = tid & 3;

    // ---- stage 128 rows: normalize, transpose, denominator ----------------
    #pragma unroll
    for (int h = 0; h < 2; h++) {
        const int sr  = h * 64 + (tid >> 2);
        const int row = qb * QROWS + sr;
        float4 qv[4];
        float ss = 0.f, dk = 0.f;
        #pragma unroll
        for (int t = 0; t < 4; t++) {
            float4 qq = Qbh[row * 16 + part + 4 * t];
            qv[t] = qq;
            ss += dot4(qq, qq);
            dk += dot4(qq, ((float4*)sKs)[part + 4 * t]);
        }
        ss += __shfl_xor_sync(0xffffffffu, ss, 1);
        ss += __shfl_xor_sync(0xffffffffu, ss, 2);
        dk += __shfl_xor_sync(0xffffffffu, dk, 1);
        dk += __shfl_xor_sync(0xffffffffu, dk, 2);
        const float sc = 1.f / fmaxf(sqrtf(ss), EPS);
        #pragma unroll
        for (int t = 0; t < 4; t++) {
            const int d0 = 4 * (part + 4 * t);
            sqT[d0 + 0][sr] = qv[t].x * sc;
            sqT[d0 + 1][sr] = qv[t].y * sc;
            sqT[d0 + 2][sr] = qv[t].z * sc;
            sqT[d0 + 3][sr] = qv[t].w * sc;
        }
        if (part == 0) sden[sr] = dk * sc + cnt;
    }
    __syncthreads();

    // ---- 8x4 register-tiled GEMM: Out = qhat^T x M ------------------------
    const int r0 = 8 * (tid >> 4);    // row base 0..120
    const int e0 = 4 * (tid & 15);    // e base 0..60

    u64 acc[4][4];                    // [row-pair][e]
    #pragma unroll
    for (int i = 0; i < 4; i++)
        #pragma unroll
        for (int j = 0; j < 4; j++) acc[i][j] = 0ull;

    #pragma unroll 8
    for (int k = 0; k < D; k++) {
        const ulonglong2 qp01 = *(const ulonglong2*)&sqT[k][r0];
        const ulonglong2 qp23 = *(const ulonglong2*)&sqT[k][r0 + 4];
        const float4     mm   = *(const float4*)&sM[k][e0];
        const u64 s0 = splat2(mm.x), s1 = splat2(mm.y);
        const u64 s2 = splat2(mm.z), s3 = splat2(mm.w);
        acc[0][0] = ffma2(qp01.x, s0, acc[0][0]);
        acc[0][1] = ffma2(qp01.x, s1, acc[0][1]);
        acc[0][2] = ffma2(qp01.x, s2, acc[0][2]);
        acc[0][3] = ffma2(qp01.x, s3, acc[0][3]);
        acc[1][0] = ffma2(qp01.y, s0, acc[1][0]);
        acc[1][1] = ffma2(qp01.y, s1, acc[1][1]);
        acc[1][2] = ffma2(qp01.y, s2, acc[1][2]);
        acc[1][3] = ffma2(qp01.y, s3, acc[1][3]);
        acc[2][0] = ffma2(qp23.x, s0, acc[2][0]);
        acc[2][1] = ffma2(qp23.x, s1, acc[2][1]);
        acc[2][2] = ffma2(qp23.x, s2, acc[2][2]);
        acc[2][3] = ffma2(qp23.x, s3, acc[2][3]);
        acc[3][0] = ffma2(qp23.y, s0, acc[3][0]);
        acc[3][1] = ffma2(qp23.y, s1, acc[3][1]);
        acc[3][2] = ffma2(qp23.y, s2, acc[3][2]);
        acc[3][3] = ffma2(qp23.y, s3, acc[3][3]);
    }

    // ---- epilogue ----------------------------------------------------------
    {
        const float4 vs = ((float4*)sVs)[tid & 15];
        const int rowbase = qb * QROWS + r0;
        #pragma unroll
        for (int i = 0; i < 4; i++) {
            const int ra = rowbase + 2 * i;
            const float inva = 1.f / sden[r0 + 2 * i];
            const float invb = 1.f / sden[r0 + 2 * i + 1];
            F2 a0, a1, a2, a3;
            a0.u = acc[i][0]; a1.u = acc[i][1]; a2.u = acc[i][2]; a3.u = acc[i][3];
            float4 oa = make_float4((a0.f.x + vs.x) * inva, (a1.f.x + vs.y) * inva,
                                    (a2.f.x + vs.z) * inva, (a3.f.x + vs.w) * inva);
            float4 ob = make_float4((a0.f.y + vs.x) * invb, (a1.f.y + vs.y) * invb,
                                    (a2.f.y + vs.z) * invb, (a3.f.y + vs.w) * invb);
            *(float4*)&Obh[(size_t)ra * 64 + e0]       = oa;
            *(float4*)&Obh[(size_t)(ra + 1) * 64 + e0] = ob;
        }
    }
}

// ===========================================================================
extern "C" void kernel_launch(void* const* d_in, const int* in_sizes, int n_in,
                              void* d_out, int out_size)
{
    const float* q    = (const float*)d_in[0];
    const float* k    = (const float*)d_in[1];
    const float* v    = (const float*)d_in[2];
    const int*   mask = (const int*)d_in[3];
    float* out = (float*)d_out;

    accum_kernel<<<dim3(BH, NCHUNK), 128>>>(k, v, mask);
    reduce_kernel<<<dim3(BH, 4), 256>>>();
    output_kernel<<<dim3(BH, NQ), 256>>>(q, out);
}

// round 12
// speedup vs baseline: 1.2582x; 1.0007x over previous
#include <cuda_runtime.h>
#include <math.h>

#define B 2
#define H 8
#define BH 16
#define S 4096
#define D 64
#define EPS 1e-12f
#define NCHUNK 32
#define CHUNK (S / NCHUNK)      // 128 key rows per accum block
#define TILE 16
#define NTILE (CHUNK / TILE)    // 8 tiles
#define NPART NCHUNK            // one M-partial per accum block
#define NQ 32
#define QROWS (S / NQ)          // 128 query rows per output block

typedef unsigned long long u64;
union F2 { u64 u; float2 f; };

// Scratch (no cudaMalloc allowed) -------------------------------------------
// M partials in "d-paired" layout: u64 index u = d2*64 + e holds
// (M[2*d2][e], M[2*d2+1][e]).
__device__ ulonglong2 g_Mpart[BH][NPART][D * D / 4];
__device__ float4     g_Kpart[BH][NPART][D / 4];
__device__ float4     g_Vpart[BH][NPART][D / 4];
__device__ float      g_cntpart[BH][NPART];

__device__ float  g_Mfin[BH][D][D];       // unpaired [d][e]
__device__ float4 g_Ksf[BH][D / 4];
__device__ float4 g_Vsf[BH][D / 4];
__device__ float  g_cntf[BH];

// ---------------------------------------------------------------------------
__device__ __forceinline__ u64 ffma2(u64 a, u64 b, u64 c) {
    u64 d;
    asm("fma.rn.f32x2 %0, %1, %2, %3;" : "=l"(d) : "l"(a), "l"(b), "l"(c));
    return d;
}
__device__ __forceinline__ u64 splat2(float s) {
    u64 d;
    asm("mov.b64 %0, {%1, %1};" : "=l"(d) : "r"(__float_as_uint(s)));
    return d;
}
__device__ __forceinline__ float dot4(float4 a, float4 b) {
    return a.x * b.x + a.y * b.y + a.z * b.z + a.w * b.w;
}
#define ADD4(a, v) { a.x += (v).x; a.y += (v).y; a.z += (v).z; a.w += (v).w; }

// ===========================================================================
// Kernel 1: per-(bh,chunk) partial of M = sum khat v^T, plus Ks, Vs, cnt.
// grid (BH, 32) = 512 blocks, 256 threads, smem 32KB.
// Software-pipelined double buffer; GEMM thread (td4, te) owns 4d x 4e,
// FFMA2-paired along d.
// ===========================================================================
__global__ __launch_bounds__(256) void accum_kernel(
    const float* __restrict__ Kt, const float* __restrict__ Vt,
    const int* __restrict__ mask)
{
    __shared__ float bufK[2][TILE][64];   // 16KB
    __shared__ float bufV[2][TILE][64];   // 16KB
    __shared__ float scred[16];

    const int bh  = blockIdx.x;
    const int ck  = blockIdx.y;
    const int b   = bh / H;
    const int tid = threadIdx.x;
    const int srw = tid >> 4;        // staging row in tile, 0..15
    const int qtr = tid & 15;        // float4 quarter of the row
    const int td4 = tid >> 4;        // d-group (4 d), 0..15
    const int te  = tid & 15;        // e-group (4 e), 0..15

    const float4* Kbh = (const float4*)(Kt + (size_t)bh * S * D);
    const float4* Vbh = (const float4*)(Vt + (size_t)bh * S * D);
    const int*    mb  = mask + (size_t)b * S;
    const int     row0 = ck * CHUNK;

    float4 ksum = make_float4(0.f,0.f,0.f,0.f);
    float4 vsum = make_float4(0.f,0.f,0.f,0.f);
    float  cacc = 0.f;

    float* curK = &bufK[0][0][0];
    float* curV = &bufV[0][0][0];
    float* nxtK = &bufK[1][0][0];
    float* nxtV = &bufV[1][0][0];

    u64 acc[2][4];                   // [d-pair][e]
    #pragma unroll
    for (int i = 0; i < 2; i++)
        #pragma unroll
        for (int j = 0; j < 4; j++) acc[i][j] = 0ull;

    float4 kr, vr;

    // ---- prologue: load + normalize + store tile 0 ------------------------
    {
        const int row = row0 + srw;
        kr = Kbh[row * 16 + qtr];
        vr = Vbh[row * 16 + qtr];
        float ss = dot4(kr, kr);
        ss += __shfl_xor_sync(0xffffffffu, ss, 1);
        ss += __shfl_xor_sync(0xffffffffu, ss, 2);
        ss += __shfl_xor_sync(0xffffffffu, ss, 4);
        ss += __shfl_xor_sync(0xffffffffu, ss, 8);
        const float m  = (float)mb[row];
        const float sc = m / fmaxf(sqrtf(ss), EPS);
        float4 kh = make_float4(kr.x*sc, kr.y*sc, kr.z*sc, kr.w*sc);
        float4 vm = make_float4(vr.x*m, vr.y*m, vr.z*m, vr.w*m);
        *(float4*)&curK[srw * 64 + 4 * qtr] = kh;
        *(float4*)&curV[srw * 64 + 4 * qtr] = vm;
        ADD4(ksum, kh);
        ADD4(vsum, vm);
        if (qtr == 0) cacc += m;
    }
    __syncthreads();

    // ---- pipelined mainloop ------------------------------------------------
    const int kOff = 4 * td4;        // float offset of this thread's K quad
    const int vOff = 4 * te;         // float offset of this thread's V quad

    for (int t = 0; t < NTILE; t++) {
        // issue next tile's loads (results consumed after the GEMM)
        if (t + 1 < NTILE) {
            const int row = row0 + (t + 1) * TILE + srw;
            kr = Kbh[row * 16 + qtr];
            vr = Vbh[row * 16 + qtr];
        }

        // GEMM: 16 rank-1 steps from current buffer (immediate LDS offsets)
        const float* cK = curK + kOff;
        const float* cV = curV + vOff;
        #pragma unroll
        for (int k = 0; k < TILE; k++) {
            const ulonglong2 ka = *(const ulonglong2*)(cK + k * 64);
            const float4     ve = *(const float4*)(cV + k * 64);
            const u64 s0 = splat2(ve.x), s1 = splat2(ve.y);
            const u64 s2 = splat2(ve.z), s3 = splat2(ve.w);
            acc[0][0] = ffma2(ka.x, s0, acc[0][0]);
            acc[0][1] = ffma2(ka.x, s1, acc[0][1]);
            acc[0][2] = ffma2(ka.x, s2, acc[0][2]);
            acc[0][3] = ffma2(ka.x, s3, acc[0][3]);
            acc[1][0] = ffma2(ka.y, s0, acc[1][0]);
            acc[1][1] = ffma2(ka.y, s1, acc[1][1]);
            acc[1][2] = ffma2(ka.y, s2, acc[1][2]);
            acc[1][3] = ffma2(ka.y, s3, acc[1][3]);
        }

        // normalize + store next tile (LDG latency now amortized)
        if (t + 1 < NTILE) {
            const int row = row0 + (t + 1) * TILE + srw;
            float ss = dot4(kr, kr);
            ss += __shfl_xor_sync(0xffffffffu, ss, 1);
            ss += __shfl_xor_sync(0xffffffffu, ss, 2);
            ss += __shfl_xor_sync(0xffffffffu, ss, 4);
            ss += __shfl_xor_sync(0xffffffffu, ss, 8);
            const float m  = (float)mb[row];
            const float sc = m / fmaxf(sqrtf(ss), EPS);
            float4 kh = make_float4(kr.x*sc, kr.y*sc, kr.z*sc, kr.w*sc);
            float4 vm = make_float4(vr.x*m, vr.y*m, vr.z*m, vr.w*m);
            *(float4*)&nxtK[srw * 64 + 4 * qtr] = kh;
            *(float4*)&nxtV[srw * 64 + 4 * qtr] = vm;
            ADD4(ksum, kh);
            ADD4(vsum, vm);
            if (qtr == 0) cacc += m;
        }
        // swap buffers
        float* tK = curK; curK = nxtK; nxtK = tK;
        float* tV = curV; curV = nxtV; nxtV = tV;
        __syncthreads();
    }

    // ---- flush M partial (paired layout: u64 u = d2*64+e) -----------------
    {
        ulonglong2* Mout = g_Mpart[bh][ck];
        #pragma unroll
        for (int i = 0; i < 2; i++) {
            const int d2 = 2 * td4 + i;           // covers d = 4td4+2i, +2i+1
            const int p0 = d2 * 32 + 2 * te;      // ulonglong2 index
            Mout[p0]     = make_ulonglong2(acc[i][0], acc[i][1]);
            Mout[p0 + 1] = make_ulonglong2(acc[i][2], acc[i][3]);
        }
    }

    // ---- reduce Ks/Vs/cnt through smem (reuse buffers) --------------------
    __syncthreads();
    float4* redK = (float4*)bufK;     // 256 float4 = 4KB
    float4* redV = (float4*)bufV;
    redK[tid] = ksum;
    redV[tid] = vsum;
    if (qtr == 0) scred[srw] = cacc;
    __syncthreads();
    if (tid < 16) {
        // column-quarter f = tid: contributors are threads row*16 + f
        float4 s = make_float4(0.f, 0.f, 0.f, 0.f);
        #pragma unroll
        for (int row = 0; row < 16; row++) {
            float4 p = redK[row * 16 + tid];
            ADD4(s, p);
        }
        g_Kpart[bh][ck][tid] = s;
    } else if (tid < 32) {
        const int f = tid - 16;
        float4 s = make_float4(0.f, 0.f, 0.f, 0.f);
        #pragma unroll
        for (int row = 0; row < 16; row++) {
            float4 p = redV[row * 16 + f];
            ADD4(s, p);
        }
        g_Vpart[bh][ck][f] = s;
    } else if (tid == 32) {
        float c = 0.f;
        #pragma unroll
        for (int i = 0; i < 16; i++) c += scred[i];
        g_cntpart[bh][ck] = c;
    }
}

// ===========================================================================
// Kernel 2: reduce partials; un-pair M into g_Mfin[d][e].
// grid (BH, 4), block 256 (each partial = 1024 float4s).
// ===========================================================================
__global__ __launch_bounds__(256) void reduce_kernel()
{
    const int bh  = blockIdx.x;
    const int yb  = blockIdx.y;
    const int tid = threadIdx.x;
    const int j   = yb * 256 + tid;   // float4 index 0..1023 within a partial

    float4 a = make_float4(0.f, 0.f, 0.f, 0.f);
    #pragma unroll 8
    for (int c = 0; c < NPART; c++) {
        float4 p = ((const float4*)g_Mpart[bh][c])[j];
        ADD4(a, p);
    }
    // float4 j = u64s {2j, 2j+1}: u0 = 2j -> d2 = u0>>6, e0 = u0&63 (even)
    const int u0 = 2 * j;
    const int d2 = u0 >> 6;           // 0..31
    const int e0 = u0 & 63;           // even, 0..62
    g_Mfin[bh][2 * d2][e0]         = a.x;
    g_Mfin[bh][2 * d2 + 1][e0]     = a.y;
    g_Mfin[bh][2 * d2][e0 + 1]     = a.z;
    g_Mfin[bh][2 * d2 + 1][e0 + 1] = a.w;

    if (yb == 0) {
        if (tid < 16) {
            float4 s = make_float4(0.f, 0.f, 0.f, 0.f);
            #pragma unroll
            for (int c = 0; c < NPART; c++) { float4 p = g_Kpart[bh][c][tid]; ADD4(s, p); }
            g_Ksf[bh][tid] = s;
        } else if (tid < 32) {
            float4 s = make_float4(0.f, 0.f, 0.f, 0.f);
            #pragma unroll
            for (int c = 0; c < NPART; c++) { float4 p = g_Vpart[bh][c][tid - 16]; ADD4(s, p); }
            g_Vsf[bh][tid - 16] = s;
        } else if (tid == 32) {
            float c0 = 0.f;
            #pragma unroll
            for (int c = 0; c < NPART; c++) c0 += g_cntpart[bh][c];
            g_cntf[bh] = c0;
        }
    }
}

// ===========================================================================
// Kernel 3: out[q,e] = (qhat . M[:,e] + Vs[e]) / (qhat . Ks + cnt)
// grid (BH, NQ), block 256, 128 rows per block in ONE pass.
// GEMM thread owns 8 rows x 4 e, FFMA2-paired along rows (sqT transposed).
// (proven version, unchanged)
// ===========================================================================
#define QT_ST 132   // multiple of 4 (16B-aligned LDS.128)

__global__ __launch_bounds__(256) void output_kernel(
    const float* __restrict__ Qt, float* __restrict__ out)
{
    const int bh  = blockIdx.x;
    const int qb  = blockIdx.y;
    const int tid = threadIdx.x;

    __shared__ float sM[D][D];          // 16KB [d][e]
    __shared__ float sqT[D][QT_ST];     // ~34KB [d][row]
    __shared__ float sKs[D];
    __shared__ float sVs[D];
    __shared__ float sden[128];
    __shared__ float scnt;

    // ---- preamble: final M / Ks / Vs / cnt --------------------------------
    {
        float4* sM4 = (float4*)sM;
        const float4* Mf = (const float4*)g_Mfin[bh];
        #pragma unroll
        for (int t = 0; t < 4; t++) sM4[tid + 256 * t] = Mf[tid + 256 * t];
        if (tid < 16)       ((float4*)sKs)[tid]      = g_Ksf[bh][tid];
        else if (tid < 32)  ((float4*)sVs)[tid - 16] = g_Vsf[bh][tid - 16];
        else if (tid == 32) scnt = g_cntf[bh];
    }
    __syncthreads();

    const float4* Qbh = (const float4*)(Qt + (size_t)bh * S * D);
    float*        Obh = out + (size_t)bh * S * D;
    const float   cnt = scnt;
    const int     part = tid & 3;

    // ---- stage 128 rows: normalize, transpose, denominator ----------------
    #pragma unroll
    for (int h = 0; h < 2; h++) {
        const int sr  = h * 64 + (tid >> 2);
        const int row = qb * QROWS + sr;
        float4 qv[4];
        float ss = 0.f, dk = 0.f;
        #pragma unroll
        for (int t = 0; t < 4; t++) {
            float4 qq = Qbh[row * 16 + part + 4 * t];
            qv[t] = qq;
            ss += dot4(qq, qq);
            dk += dot4(qq, ((float4*)sKs)[part + 4 * t]);
        }
        ss += __shfl_xor_sync(0xffffffffu, ss, 1);
        ss += __shfl_xor_sync(0xffffffffu, ss, 2);
        dk += __shfl_xor_sync(0xffffffffu, dk, 1);
        dk += __shfl_xor_sync(0xffffffffu, dk, 2);
        const float sc = 1.f / fmaxf(sqrtf(ss), EPS);
        #pragma unroll
        for (int t = 0; t < 4; t++) {
            const int d0 = 4 * (part + 4 * t);
            sqT[d0 + 0][sr] = qv[t].x * sc;
            sqT[d0 + 1][sr] = qv[t].y * sc;
            sqT[d0 + 2][sr] = qv[t].z * sc;
            sqT[d0 + 3][sr] = qv[t].w * sc;
        }
        if (part == 0) sden[sr] = dk * sc + cnt;
    }
    __syncthreads();

    // ---- 8x4 register-tiled GEMM: Out = qhat^T x M ------------------------
    const int r0 = 8 * (tid >> 4);    // row base 0..120
    const int e0 = 4 * (tid & 15);    // e base 0..60

    u64 acc[4][4];                    // [row-pair][e]
    #pragma unroll
    for (int i = 0; i < 4; i++)
        #pragma unroll
        for (int j = 0; j < 4; j++) acc[i][j] = 0ull;

    #pragma unroll 8
    for (int k = 0; k < D; k++) {
        const ulonglong2 qp01 = *(const ulonglong2*)&sqT[k][r0];
        const ulonglong2 qp23 = *(const ulonglong2*)&sqT[k][r0 + 4];
        const float4     mm   = *(const float4*)&sM[k][e0];
        const u64 s0 = splat2(mm.x), s1 = splat2(mm.y);
        const u64 s2 = splat2(mm.z), s3 = splat2(mm.w);
        acc[0][0] = ffma2(qp01.x, s0, acc[0][0]);
        acc[0][1] = ffma2(qp01.x, s1, acc[0][1]);
        acc[0][2] = ffma2(qp01.x, s2, acc[0][2]);
        acc[0][3] = ffma2(qp01.x, s3, acc[0][3]);
        acc[1][0] = ffma2(qp01.y, s0, acc[1][0]);
        acc[1][1] = ffma2(qp01.y, s1, acc[1][1]);
        acc[1][2] = ffma2(qp01.y, s2, acc[1][2]);
        acc[1][3] = ffma2(qp01.y, s3, acc[1][3]);
        acc[2][0] = ffma2(qp23.x, s0, acc[2][0]);
        acc[2][1] = ffma2(qp23.x, s1, acc[2][1]);
        acc[2][2] = ffma2(qp23.x, s2, acc[2][2]);
        acc[2][3] = ffma2(qp23.x, s3, acc[2][3]);
        acc[3][0] = ffma2(qp23.y, s0, acc[3][0]);
        acc[3][1] = ffma2(qp23.y, s1, acc[3][1]);
        acc[3][2] = ffma2(qp23.y, s2, acc[3][2]);
        acc[3][3] = ffma2(qp23.y, s3, acc[3][3]);
    }

    // ---- epilogue ----------------------------------------------------------
    {
        const float4 vs = ((float4*)sVs)[tid & 15];
        const int rowbase = qb * QROWS + r0;
        #pragma unroll
        for (int i = 0; i < 4; i++) {
            const int ra = rowbase + 2 * i;
            const float inva = 1.f / sden[r0 + 2 * i];
            const float invb = 1.f / sden[r0 + 2 * i + 1];
            F2 a0, a1, a2, a3;
            a0.u = acc[i][0]; a1.u = acc[i][1]; a2.u = acc[i][2]; a3.u = acc[i][3];
            float4 oa = make_float4((a0.f.x + vs.x) * inva, (a1.f.x + vs.y) * inva,
                                    (a2.f.x + vs.z) * inva, (a3.f.x + vs.w) * inva);
            float4 ob = make_float4((a0.f.y + vs.x) * invb, (a1.f.y + vs.y) * invb,
                                    (a2.f.y + vs.z) * invb, (a3.f.y + vs.w) * invb);
            *(float4*)&Obh[(size_t)ra * 64 + e0]       = oa;
            *(float4*)&Obh[(size_t)(ra + 1) * 64 + e0] = ob;
        }
    }
}

// ===========================================================================
extern "C" void kernel_launch(void* const* d_in, const int* in_sizes, int n_in,
                              void* d_out, int out_size)
{
    const float* q    = (const float*)d_in[0];
    const float* k    = (const float*)d_in[1];
    const float* v    = (const float*)d_in[2];
    const int*   mask = (const int*)d_in[3];
    float* out = (float*)d_out;

    accum_kernel<<<dim3(BH, NCHUNK), 256>>>(k, v, mask);
    reduce_kernel<<<dim3(BH, 4), 256>>>();
    output_kernel<<<dim3(BH, NQ), 256>>>(q, out);
}